// round 14
// baseline (speedup 1.0000x reference)
#include <cuda_runtime.h>
#include <cuda_bf16.h>
#include <cstdint>

// Problem constants
#define BB   4096
#define AA   8
#define HH   512
#define NQv  128
#define NKv  128
#define NVv  256
#define NACT 30
#define ROWS (BB*AA)              // 32768
#define ORI_OFF  (ROWS*NACT)
#define COM_OFF  (ORI_OFF + ROWS)

// ---------------- device scratch (static, allocation-free) ----------------
__device__ float    g_kvq[(size_t)ROWS * HH];     // GEMM1 output (fp32)
__device__ float    g_comb[(size_t)ROWS * HH];    // GEMM2 output (fp32)
__device__ float    g_allev[(size_t)BB * NACT];
__device__ unsigned g_scal[4];
__device__ float    g_b1[HH];
// hi/lo bf16 A-side operands
__device__ __nv_bfloat16 g_Ah[(size_t)ROWS * HH];   // hidden hi
__device__ __nv_bfloat16 g_Al[(size_t)ROWS * HH];   // hidden lo
__device__ __nv_bfloat16 g_ATh[(size_t)ROWS * NVv]; // attn hi
__device__ __nv_bfloat16 g_ATl[(size_t)ROWS * NVv]; // attn lo
// transposed, hi/lo bf16 weights: WT[n][k]
__device__ __nv_bfloat16 g_WT1h[HH * HH];
__device__ __nv_bfloat16 g_WT1l[HH * HH];
__device__ __nv_bfloat16 g_WTch[HH * (NVv + HH)];
__device__ __nv_bfloat16 g_WTcl[HH * (NVv + HH)];

// order-preserving float<->uint mapping for atomic min/max
__device__ __forceinline__ unsigned fkey(float f) {
    unsigned u = __float_as_uint(f);
    return (u >> 31) ? ~u : (u | 0x80000000u);
}
__device__ __forceinline__ float funkey(unsigned k) {
    unsigned u = (k >> 31) ? (k ^ 0x80000000u) : ~k;
    return __uint_as_float(u);
}

// bf16 mma.sync (family-portable HMMA)
__device__ __forceinline__ void mma_bf16(float* d, const uint32_t* a, const uint32_t* b) {
    asm volatile(
        "mma.sync.aligned.m16n8k16.row.col.f32.bf16.bf16.f32 "
        "{%0,%1,%2,%3}, {%4,%5,%6,%7}, {%8,%9}, {%0,%1,%2,%3};"
        : "+f"(d[0]), "+f"(d[1]), "+f"(d[2]), "+f"(d[3])
        : "r"(a[0]), "r"(a[1]), "r"(a[2]), "r"(a[3]), "r"(b[0]), "r"(b[1]));
}
__device__ __forceinline__ void ldsm_x4(uint32_t* r, uint32_t addr) {
    asm volatile("ldmatrix.sync.aligned.m8n8.x4.shared.b16 {%0,%1,%2,%3}, [%4];"
        : "=r"(r[0]), "=r"(r[1]), "=r"(r[2]), "=r"(r[3]) : "r"(addr));
}
__device__ __forceinline__ void ldsm_x2(uint32_t* r, uint32_t addr) {
    asm volatile("ldmatrix.sync.aligned.m8n8.x2.shared.b16 {%0,%1}, [%2];"
        : "=r"(r[0]), "=r"(r[1]) : "r"(addr));
}
#define CP16(dst, src) \
    asm volatile("cp.async.cg.shared.global [%0], [%1], 16;" :: "r"(dst), "l"(src))

__device__ __forceinline__ void cvt_hilo2(float x, float y, uint32_t& hi, uint32_t& lo) {
    __nv_bfloat162 h = __floats2bfloat162_rn(x, y);
    float hx = __bfloat162float(h.x), hy = __bfloat162float(h.y);
    __nv_bfloat162 l = __floats2bfloat162_rn(x - hx, y - hy);
    hi = *(uint32_t*)&h;
    lo = *(uint32_t*)&l;
}

// ---------------- init ----------------
__global__ void init_kernel() {
    if (threadIdx.x == 0) {
        g_scal[0] = 0u; g_scal[1] = 0xFFFFFFFFu;
        g_scal[2] = 0u; g_scal[3] = 0xFFFFFFFFu;
    }
}

// ---------------- convert hidden fp32 -> hi/lo bf16 ----------------
__global__ __launch_bounds__(256)
void convA_kernel(const float* __restrict__ src) {
    int i = blockIdx.x * blockDim.x + threadIdx.x;   // one float4 per thread
    float4 v = ((const float4*)src)[i];
    uint32_t h01, l01, h23, l23;
    cvt_hilo2(v.x, v.y, h01, l01);
    cvt_hilo2(v.z, v.w, h23, l23);
    ((uint2*)g_Ah)[i] = make_uint2(h01, h23);
    ((uint2*)g_Al)[i] = make_uint2(l01, l23);
}

// ---------------- pack W1 (Wk|Wv|Wq) -> transposed hi/lo bf16, b1 ----------------
__global__ void pack1_kernel(const float* __restrict__ Wk, const float* __restrict__ bk,
                             const float* __restrict__ Wv, const float* __restrict__ bv,
                             const float* __restrict__ Wq, const float* __restrict__ bq) {
    int i = blockIdx.x * blockDim.x + threadIdx.x;
    if (i < HH * HH) {
        int n = i >> 9, k = i & 511;
        float w;
        if (n < NKv)            w = Wk[k * NKv + n];
        else if (n < NKv + NVv) w = Wv[k * NVv + (n - NKv)];
        else                    w = Wq[k * NQv + (n - NKv - NVv)];
        __nv_bfloat16 h = __float2bfloat16(w);
        g_WT1h[i] = h;
        g_WT1l[i] = __float2bfloat16(w - __bfloat162float(h));
    }
    if (i < HH) {
        float v;
        if (i < NKv)            v = bk[i];
        else if (i < NKv + NVv) v = bv[i - NKv];
        else                    v = bq[i - NKv - NVv];
        g_b1[i] = v;
    }
}

// ---------------- pack Wc -> transposed hi/lo bf16 ----------------
__global__ void packc_kernel(const float* __restrict__ Wc) {
    int i = blockIdx.x * blockDim.x + threadIdx.x;
    if (i < HH * (NVv + HH)) {
        int n = i / (NVv + HH), k = i % (NVv + HH);
        float w = Wc[k * HH + n];
        __nv_bfloat16 h = __float2bfloat16(w);
        g_WTch[i] = h;
        g_WTcl[i] = __float2bfloat16(w - __bfloat162float(h));
    }
}

// ---------------- HMMA GEMM: C[M,N] = act(A @ WT^T + bias) ----------------
// All operands bf16 hi/lo in gmem. A split by K (A0* for k<K0, A1* after).
// Block tile 128x128x32, 8 warps (2x4), warp tile 64x32.
// Double-buffered smem, cp.async for A+B, ldmatrix fragment loads.
// hi/lo compensation: D += Ah*Bh + Ah*Bl + Al*Bh.
#define GSTR 40                      // padded k-stride in bf16 elems (80B, LDSM conflict-free)
#define TILE_B (128 * GSTR * 2)      // 10240 bytes per sub-tile
#define BUF_B  (4 * TILE_B)          // Ah|Al|Bh|Bl = 40960 bytes
#define GEMM_SMEM (2 * BUF_B)        // 81920

template<bool RELU>
__global__ __launch_bounds__(256, 2)
void gemm_mma(const __nv_bfloat16* __restrict__ A0h, const __nv_bfloat16* __restrict__ A0l,
              int lda0, int K0,
              const __nv_bfloat16* __restrict__ A1h, const __nv_bfloat16* __restrict__ A1l,
              int lda1,
              const __nv_bfloat16* __restrict__ WTh, const __nv_bfloat16* __restrict__ WTl,
              const float* __restrict__ bias, float* __restrict__ C, int N, int K) {
    extern __shared__ char sm[];
    uint32_t sbase = (uint32_t)__cvta_generic_to_shared(sm);
    int tid = threadIdx.x;
    int wid = tid >> 5, lane = tid & 31;
    int gid = lane >> 2, tig = lane & 3;
    int wr = wid >> 2, wc = wid & 3;           // 2 x 4 warp grid
    int rowC = blockIdx.y * 128;
    int colC = blockIdx.x * 128;

    int r = tid >> 1, kh = (tid & 1) * 16;     // cp.async mapping: row r, 16 bf16

    // ldmatrix per-lane offsets
    int aRow = wr * 64 + (lane & 15);
    int aK   = (lane >> 4) * 8;
    int bRow = wc * 32 + (lane & 7);
    int bK   = ((lane >> 3) & 1) * 8;

    float acc[4][4][4];
    #pragma unroll
    for (int mi = 0; mi < 4; mi++)
        #pragma unroll
        for (int ni = 0; ni < 4; ni++)
            #pragma unroll
            for (int j = 0; j < 4; j++) acc[mi][ni][j] = 0.f;

    auto cp_chunk = [&](int kb, int b) {
        uint32_t off = (uint32_t)b * BUF_B + (uint32_t)(r * GSTR + kh) * 2;
        // A hi/lo
        const __nv_bfloat16 *sh, *sl; int lda;
        if (kb < K0) { sh = A0h + kb; sl = A0l + kb; lda = lda0; }
        else         { sh = A1h + (kb - K0); sl = A1l + (kb - K0); lda = lda1; }
        const __nv_bfloat16* pah = sh + (size_t)(rowC + r) * lda + kh;
        const __nv_bfloat16* pal = sl + (size_t)(rowC + r) * lda + kh;
        CP16(sbase + off,               pah);
        CP16(sbase + off + 16,          pah + 8);
        CP16(sbase + TILE_B + off,      pal);
        CP16(sbase + TILE_B + off + 16, pal + 8);
        // B hi/lo
        const __nv_bfloat16* pbh = WTh + (size_t)(colC + r) * K + kb + kh;
        const __nv_bfloat16* pbl = WTl + (size_t)(colC + r) * K + kb + kh;
        CP16(sbase + 2 * TILE_B + off,      pbh);
        CP16(sbase + 2 * TILE_B + off + 16, pbh + 8);
        CP16(sbase + 3 * TILE_B + off,      pbl);
        CP16(sbase + 3 * TILE_B + off + 16, pbl + 8);
        asm volatile("cp.async.commit_group;");
    };
    auto compute = [&](int b) {
        uint32_t base = sbase + b * BUF_B;
        #pragma unroll
        for (int ks = 0; ks < 32; ks += 16) {
            uint32_t bh[4][2], bl[4][2];
            #pragma unroll
            for (int ni = 0; ni < 4; ni++) {
                uint32_t ab = base + 2 * TILE_B + (uint32_t)((bRow + ni * 8) * GSTR + ks + bK) * 2;
                ldsm_x2(bh[ni], ab);
                ldsm_x2(bl[ni], ab + TILE_B);
            }
            #pragma unroll
            for (int mi = 0; mi < 4; mi++) {
                uint32_t aa = base + (uint32_t)((aRow + mi * 16) * GSTR + ks + aK) * 2;
                uint32_t a[4], al[4];
                ldsm_x4(a,  aa);
                ldsm_x4(al, aa + TILE_B);
                #pragma unroll
                for (int ni = 0; ni < 4; ni++) mma_bf16(acc[mi][ni], a,  bh[ni]);
                #pragma unroll
                for (int ni = 0; ni < 4; ni++) mma_bf16(acc[mi][ni], a,  bl[ni]);
                #pragma unroll
                for (int ni = 0; ni < 4; ni++) mma_bf16(acc[mi][ni], al, bh[ni]);
            }
        }
    };

    int nch = K / 32;
    cp_chunk(0, 0);
    for (int c = 0; c < nch; c++) {
        if (c + 1 < nch) {
            cp_chunk((c + 1) * 32, (c + 1) & 1);
            asm volatile("cp.async.wait_group 1;");
        } else {
            asm volatile("cp.async.wait_group 0;");
        }
        __syncthreads();
        compute(c & 1);
        __syncthreads();
    }

    // epilogue
    #pragma unroll
    for (int mi = 0; mi < 4; mi++) {
        int row0 = rowC + wr * 64 + mi * 16 + gid;
        #pragma unroll
        for (int ni = 0; ni < 4; ni++) {
            int col = colC + wc * 32 + ni * 8 + tig * 2;
            float bx = __ldg(&bias[col]), by = __ldg(&bias[col + 1]);
            float2 o0 = make_float2(acc[mi][ni][0] + bx, acc[mi][ni][1] + by);
            float2 o1 = make_float2(acc[mi][ni][2] + bx, acc[mi][ni][3] + by);
            if (RELU) {
                o0.x = fmaxf(o0.x, 0.f); o0.y = fmaxf(o0.y, 0.f);
                o1.x = fmaxf(o1.x, 0.f); o1.y = fmaxf(o1.y, 0.f);
            }
            *(float2*)(C + (size_t)row0 * N + col) = o0;
            *(float2*)(C + (size_t)(row0 + 8) * N + col) = o1;
        }
    }
}

// ---------------- per-batch attention (writes hi/lo bf16) ----------------
__global__ __launch_bounds__(256)
void attn_kernel(const float* __restrict__ kvq, const float* __restrict__ Wattn,
                 const float* __restrict__ battn) {
    int b = blockIdx.x;
    int tid = threadIdx.x;
    __shared__ float sk[AA * NKv];
    __shared__ float sq[AA * NQv];
    __shared__ float sv[AA * NVv];
    __shared__ float slog[AA][AA];
    __shared__ float swt[AA][AA + 1];
    __shared__ float skp[AA];
    const float* base = kvq + (size_t)b * AA * HH;
    {
        int a = tid >> 5, c = (tid & 31) * 4;
        *(float4*)&sk[a * NKv + c] = *(const float4*)&base[a * HH + c];
        *(float4*)&sq[a * NQv + c] = *(const float4*)&base[a * HH + 384 + c];
    }
    for (int i = tid; i < AA * NVv / 4; i += 256) {
        int a = i >> 6, c = (i & 63) * 4;
        *(float4*)&sv[a * NVv + c] = *(const float4*)&base[a * HH + 128 + c];
    }
    __syncthreads();
    int w = tid >> 5, lane = tid & 31;
    float kp = 0.f;
    for (int i = lane; i < AA * NKv; i += 32)
        kp += sk[i] * __ldg(&Wattn[(NQv + i) * AA + w]);
    #pragma unroll
    for (int o = 16; o; o >>= 1) kp += __shfl_xor_sync(0xFFFFFFFFu, kp, o);
    if (lane == 0) skp[w] = kp;
    __syncthreads();
    float accj[AA] = {0,0,0,0,0,0,0,0};
    for (int q = lane; q < NQv; q += 32) {
        float qv = sq[w * NQv + q];
        #pragma unroll
        for (int j = 0; j < AA; j++) accj[j] += qv * __ldg(&Wattn[q * AA + j]);
    }
    #pragma unroll
    for (int j = 0; j < AA; j++) {
        float v = accj[j];
        #pragma unroll
        for (int o = 16; o; o >>= 1) v += __shfl_xor_sync(0xFFFFFFFFu, v, o);
        if (lane == 0) slog[w][j] = v + skp[j] + __ldg(&battn[j]);
    }
    __syncthreads();
    if (tid < AA) {
        float m = -1e30f;
        #pragma unroll
        for (int j = 0; j < AA; j++) m = fmaxf(m, slog[tid][j]);
        float e[AA], s = 0.f;
        #pragma unroll
        for (int j = 0; j < AA; j++) { e[j] = expf(slog[tid][j] - m); s += e[j]; }
        #pragma unroll
        for (int j = 0; j < AA; j++) swt[tid][j] = e[j] / s;
    }
    __syncthreads();
    for (int idx = tid; idx < AA * NVv / 4; idx += 256) {
        int a = idx >> 6, v = (idx & 63) * 4;
        float4 acc = make_float4(0.f, 0.f, 0.f, 0.f);
        #pragma unroll
        for (int j = 0; j < AA; j++) {
            float wt = swt[a][j];
            float4 s4 = *(const float4*)&sv[j * NVv + v];
            acc.x += wt * s4.x; acc.y += wt * s4.y;
            acc.z += wt * s4.z; acc.w += wt * s4.w;
        }
        uint32_t h01, l01, h23, l23;
        cvt_hilo2(acc.x, acc.y, h01, l01);
        cvt_hilo2(acc.z, acc.w, h23, l23);
        size_t elem = (size_t)(b * AA + a) * NVv + v;   // multiple of 4
        ((uint2*)g_ATh)[elem >> 2] = make_uint2(h01, h23);
        ((uint2*)g_ATl)[elem >> 2] = make_uint2(l01, l23);
    }
}

// ---------------- W2 head ----------------
__global__ __launch_bounds__(256)
void head_kernel(const float* __restrict__ comb, const float* __restrict__ W2,
                 const float* __restrict__ b2, float* __restrict__ out) {
    __shared__ float srow[8][HH];
    __shared__ float smx[8], smn[8];
    int w = threadIdx.x >> 5, lane = threadIdx.x & 31;
    int row = blockIdx.x * 8 + w;
    const float* a = comb + (size_t)row * HH;
    for (int i = lane * 4; i < HH; i += 128) *(float4*)&srow[w][i] = *(const float4*)&a[i];
    __syncwarp();
    float acc = 0.f;
    if (lane < NACT) {
        #pragma unroll 8
        for (int k = 0; k < HH; k++) acc += srow[w][k] * __ldg(&W2[k * NACT + lane]);
        acc += __ldg(&b2[lane]);
    }
    float be = (lane < NACT) ? fmaxf(acc, 0.f) : 0.f;
    if (lane < NACT) out[(size_t)row * NACT + lane] = be;
    float s = be;
    #pragma unroll
    for (int o = 16; o; o >>= 1) s += __shfl_xor_sync(0xFFFFFFFFu, s, o);
    s += (float)NACT;
    if (lane == 0) {
        int bb = row >> 3, aa = row & 7;
        out[ORI_OFF + aa * BB + bb] = (float)NACT / s;
    }
    float mx = be;
    float mn = (lane < NACT) ? be : 1e30f;
    #pragma unroll
    for (int o = 16; o; o >>= 1) {
        mx = fmaxf(mx, __shfl_xor_sync(0xFFFFFFFFu, mx, o));
        mn = fminf(mn, __shfl_xor_sync(0xFFFFFFFFu, mn, o));
    }
    if (lane == 0) { smx[w] = mx; smn[w] = mn; }
    __syncthreads();
    if (threadIdx.x == 0) {
        float M = -1e30f, m = 1e30f;
        #pragma unroll
        for (int i = 0; i < 8; i++) { M = fmaxf(M, smx[i]); m = fminf(m, smn[i]); }
        atomicMax(&g_scal[0], fkey(M));
        atomicMin(&g_scal[1], fkey(m));
    }
}

// ---------------- Dempster-Shafer scan ----------------
__global__ __launch_bounds__(256)
void ds_kernel(const float* __restrict__ out, float* __restrict__ allev) {
    __shared__ float smx[8], smn[8];
    int w = threadIdx.x >> 5, lane = threadIdx.x & 31;
    int b = blockIdx.x * 8 + w;
    float b0 = 0.f, u0 = 1.f;
    for (int a = 0; a < AA; a++) {
        float e = (lane < NACT) ? out[(size_t)(b * AA + a) * NACT + lane] : 0.f;
        float s = e;
        #pragma unroll
        for (int o = 16; o; o >>= 1) s += __shfl_xor_sync(0xFFFFFFFFu, s, o);
        s += (float)NACT;
        float b1 = e / s;
        float u1 = (float)NACT / s;
        float sum0 = b0, sum1 = b1, dot = b0 * b1;
        #pragma unroll
        for (int o = 16; o; o >>= 1) {
            sum0 += __shfl_xor_sync(0xFFFFFFFFu, sum0, o);
            sum1 += __shfl_xor_sync(0xFFFFFFFFu, sum1, o);
            dot  += __shfl_xor_sync(0xFFFFFFFFu, dot,  o);
        }
        float Cc = sum0 * sum1 - dot;
        float denom = 1.f - Cc;
        float nb = (b0 * b1 + b0 * u1 + b1 * u0) / denom;
        u0 = (u0 * u1) / denom;
        b0 = nb;
    }
    float ev = b0 * ((float)NACT / u0);
    if (lane < NACT) allev[(size_t)b * NACT + lane] = ev;
    float mx = (lane < NACT) ? ev : -1e30f;
    float mn = (lane < NACT) ? ev : 1e30f;
    #pragma unroll
    for (int o = 16; o; o >>= 1) {
        mx = fmaxf(mx, __shfl_xor_sync(0xFFFFFFFFu, mx, o));
        mn = fminf(mn, __shfl_xor_sync(0xFFFFFFFFu, mn, o));
    }
    if (lane == 0) { smx[w] = mx; smn[w] = mn; }
    __syncthreads();
    if (threadIdx.x == 0) {
        float M = -1e30f, m = 1e30f;
        #pragma unroll
        for (int i = 0; i < 8; i++) { M = fmaxf(M, smx[i]); m = fminf(m, smn[i]); }
        atomicMax(&g_scal[2], fkey(M));
        atomicMin(&g_scal[3], fkey(m));
    }
}

// ---------------- finalize ----------------
__global__ __launch_bounds__(256)
void fin_kernel(float* __restrict__ out, const float* __restrict__ allev) {
    float maxbe = funkey(g_scal[0]);
    float minbe = funkey(g_scal[1]);
    float maxre = funkey(g_scal[2]);
    float minre = funkey(g_scal[3]);
    float scale = (maxbe - minbe) * 0.1f;
    float norm = scale / (maxre - minre + 0.01f);
    int w = threadIdx.x >> 5, lane = threadIdx.x & 31;
    int row = blockIdx.x * 8 + w;
    int b = row >> 3, a = row & 7;
    float be = (lane < NACT) ? out[(size_t)row * NACT + lane] : 0.f;
    float ev = (lane < NACT) ? allev[(size_t)b * NACT + lane] : 0.f;
    float re = (ev - minre) * norm;
    float combined = be + re;
    if (lane < NACT) out[(size_t)row * NACT + lane] = be + combined;
    float s = (lane < NACT) ? combined : 0.f;
    #pragma unroll
    for (int o = 16; o; o >>= 1) s += __shfl_xor_sync(0xFFFFFFFFu, s, o);
    s += (float)NACT;
    if (lane == 0) out[COM_OFF + a * BB + b] = (float)NACT / s;
}

// ---------------- launch ----------------
extern "C" void kernel_launch(void* const* d_in, const int* in_sizes, int n_in,
                              void* d_out, int out_size) {
    const float* hidden = (const float*)d_in[0];
    const float* Wk    = (const float*)d_in[2];
    const float* bk    = (const float*)d_in[3];
    const float* Wv    = (const float*)d_in[4];
    const float* bv    = (const float*)d_in[5];
    const float* Wq    = (const float*)d_in[6];
    const float* bq    = (const float*)d_in[7];
    const float* Wattn = (const float*)d_in[8];
    const float* battn = (const float*)d_in[9];
    const float* Wc    = (const float*)d_in[10];
    const float* bc    = (const float*)d_in[11];
    const float* W2    = (const float*)d_in[12];
    const float* b2    = (const float*)d_in[13];
    float* out = (float*)d_out;

    float *kvq, *comb, *allev, *b1;
    __nv_bfloat16 *ah, *al, *ath, *atl, *wt1h, *wt1l, *wtch, *wtcl;
    cudaGetSymbolAddress((void**)&kvq,   g_kvq);
    cudaGetSymbolAddress((void**)&comb,  g_comb);
    cudaGetSymbolAddress((void**)&allev, g_allev);
    cudaGetSymbolAddress((void**)&b1,    g_b1);
    cudaGetSymbolAddress((void**)&ah,    g_Ah);
    cudaGetSymbolAddress((void**)&al,    g_Al);
    cudaGetSymbolAddress((void**)&ath,   g_ATh);
    cudaGetSymbolAddress((void**)&atl,   g_ATl);
    cudaGetSymbolAddress((void**)&wt1h,  g_WT1h);
    cudaGetSymbolAddress((void**)&wt1l,  g_WT1l);
    cudaGetSymbolAddress((void**)&wtch,  g_WTch);
    cudaGetSymbolAddress((void**)&wtcl,  g_WTcl);

    cudaFuncSetAttribute(gemm_mma<false>, cudaFuncAttributeMaxDynamicSharedMemorySize, GEMM_SMEM);
    cudaFuncSetAttribute(gemm_mma<true>,  cudaFuncAttributeMaxDynamicSharedMemorySize, GEMM_SMEM);

    init_kernel<<<1, 32>>>();
    convA_kernel<<<ROWS * HH / 4 / 256, 256>>>(hidden);
    pack1_kernel<<<(HH * HH + 255) / 256, 256>>>(Wk, bk, Wv, bv, Wq, bq);
    packc_kernel<<<(HH * (NVv + HH) + 255) / 256, 256>>>(Wc);

    dim3 g1(HH / 128, ROWS / 128);   // (4, 256)
    gemm_mma<false><<<g1, 256, GEMM_SMEM>>>(ah, al, HH, HH, ah, al, HH,
                                            wt1h, wt1l, b1, kvq, HH, HH);

    attn_kernel<<<BB, 256>>>(kvq, Wattn, battn);

    gemm_mma<true><<<g1, 256, GEMM_SMEM>>>(ath, atl, NVv, NVv, ah, al, HH,
                                           wtch, wtcl, bc, comb, HH, NVv + HH);

    head_kernel<<<ROWS / 8, 256>>>(comb, W2, b2, out);
    ds_kernel<<<BB / 8, 256>>>(out, allev);
    fin_kernel<<<ROWS / 8, 256>>>(out, allev);
}

// round 17
// speedup vs baseline: 1.0994x; 1.0994x over previous
#include <cuda_runtime.h>
#include <cuda_bf16.h>
#include <cstdint>

// Problem constants
#define BB   4096
#define AA   8
#define HH   512
#define NQv  128
#define NKv  128
#define NVv  256
#define NACT 30
#define ROWS (BB*AA)              // 32768
#define ORI_OFF  (ROWS*NACT)
#define COM_OFF  (ORI_OFF + ROWS)

// ---------------- device scratch (static, allocation-free) ----------------
__device__ float    g_kvq[(size_t)ROWS * HH];     // GEMM1 output (fp32)
__device__ float    g_allev[(size_t)BB * NACT];
__device__ unsigned g_scal[4];
__device__ float    g_b1[HH];
// hi/lo bf16 operands
__device__ __nv_bfloat16 g_Ah[(size_t)ROWS * HH];    // hidden hi
__device__ __nv_bfloat16 g_Al[(size_t)ROWS * HH];    // hidden lo
__device__ __nv_bfloat16 g_ATh[(size_t)ROWS * NVv];  // attn hi
__device__ __nv_bfloat16 g_ATl[(size_t)ROWS * NVv];  // attn lo
__device__ __nv_bfloat16 g_Ch[(size_t)ROWS * HH];    // comb hi (GEMM2 out)
__device__ __nv_bfloat16 g_Cl[(size_t)ROWS * HH];    // comb lo
// transposed, hi/lo bf16 weights: WT[n][k]
__device__ __nv_bfloat16 g_WT1h[HH * HH];
__device__ __nv_bfloat16 g_WT1l[HH * HH];
__device__ __nv_bfloat16 g_WTch[HH * (NVv + HH)];
__device__ __nv_bfloat16 g_WTcl[HH * (NVv + HH)];
__device__ __nv_bfloat16 g_W2Th[32 * HH];            // W2^T padded to 32 rows
__device__ __nv_bfloat16 g_W2Tl[32 * HH];

// order-preserving float<->uint mapping for atomic min/max
__device__ __forceinline__ unsigned fkey(float f) {
    unsigned u = __float_as_uint(f);
    return (u >> 31) ? ~u : (u | 0x80000000u);
}
__device__ __forceinline__ float funkey(unsigned k) {
    unsigned u = (k >> 31) ? (k ^ 0x80000000u) : ~k;
    return __uint_as_float(u);
}

// bf16 mma.sync (family-portable HMMA)
__device__ __forceinline__ void mma_bf16(float* d, const uint32_t* a, const uint32_t* b) {
    asm volatile(
        "mma.sync.aligned.m16n8k16.row.col.f32.bf16.bf16.f32 "
        "{%0,%1,%2,%3}, {%4,%5,%6,%7}, {%8,%9}, {%0,%1,%2,%3};"
        : "+f"(d[0]), "+f"(d[1]), "+f"(d[2]), "+f"(d[3])
        : "r"(a[0]), "r"(a[1]), "r"(a[2]), "r"(a[3]), "r"(b[0]), "r"(b[1]));
}
__device__ __forceinline__ void ldsm_x4(uint32_t* r, uint32_t addr) {
    asm volatile("ldmatrix.sync.aligned.m8n8.x4.shared.b16 {%0,%1,%2,%3}, [%4];"
        : "=r"(r[0]), "=r"(r[1]), "=r"(r[2]), "=r"(r[3]) : "r"(addr));
}
__device__ __forceinline__ void ldsm_x2(uint32_t* r, uint32_t addr) {
    asm volatile("ldmatrix.sync.aligned.m8n8.x2.shared.b16 {%0,%1}, [%2];"
        : "=r"(r[0]), "=r"(r[1]) : "r"(addr));
}
#define CP16(dst, src) \
    asm volatile("cp.async.cg.shared.global [%0], [%1], 16;" :: "r"(dst), "l"(src))

__device__ __forceinline__ void cvt_hilo2(float x, float y, uint32_t& hi, uint32_t& lo) {
    __nv_bfloat162 h = __floats2bfloat162_rn(x, y);
    float hx = __bfloat162float(h.x), hy = __bfloat162float(h.y);
    __nv_bfloat162 l = __floats2bfloat162_rn(x - hx, y - hy);
    hi = *(uint32_t*)&h;
    lo = *(uint32_t*)&l;
}

// ---------------- init ----------------
__global__ void init_kernel() {
    if (threadIdx.x == 0) {
        g_scal[0] = 0u; g_scal[1] = 0xFFFFFFFFu;
        g_scal[2] = 0u; g_scal[3] = 0xFFFFFFFFu;
    }
}

// ---------------- convert hidden fp32 -> hi/lo bf16 ----------------
__global__ __launch_bounds__(256)
void convA_kernel(const float* __restrict__ src) {
    int i = blockIdx.x * blockDim.x + threadIdx.x;   // one float4 per thread
    float4 v = ((const float4*)src)[i];
    uint32_t h01, l01, h23, l23;
    cvt_hilo2(v.x, v.y, h01, l01);
    cvt_hilo2(v.z, v.w, h23, l23);
    ((uint2*)g_Ah)[i] = make_uint2(h01, h23);
    ((uint2*)g_Al)[i] = make_uint2(l01, l23);
}

// ---------------- pack W1 (Wk|Wv|Wq) -> transposed hi/lo bf16, b1 ----------------
__global__ void pack1_kernel(const float* __restrict__ Wk, const float* __restrict__ bk,
                             const float* __restrict__ Wv, const float* __restrict__ bv,
                             const float* __restrict__ Wq, const float* __restrict__ bq) {
    int i = blockIdx.x * blockDim.x + threadIdx.x;
    if (i < HH * HH) {
        int n = i >> 9, k = i & 511;
        float w;
        if (n < NKv)            w = Wk[k * NKv + n];
        else if (n < NKv + NVv) w = Wv[k * NVv + (n - NKv)];
        else                    w = Wq[k * NQv + (n - NKv - NVv)];
        __nv_bfloat16 h = __float2bfloat16(w);
        g_WT1h[i] = h;
        g_WT1l[i] = __float2bfloat16(w - __bfloat162float(h));
    }
    if (i < HH) {
        float v;
        if (i < NKv)            v = bk[i];
        else if (i < NKv + NVv) v = bv[i - NKv];
        else                    v = bq[i - NKv - NVv];
        g_b1[i] = v;
    }
}

// ---------------- pack Wc -> transposed hi/lo bf16 ----------------
__global__ void packc_kernel(const float* __restrict__ Wc) {
    int i = blockIdx.x * blockDim.x + threadIdx.x;
    if (i < HH * (NVv + HH)) {
        int n = i / (NVv + HH), k = i % (NVv + HH);
        float w = Wc[k * HH + n];
        __nv_bfloat16 h = __float2bfloat16(w);
        g_WTch[i] = h;
        g_WTcl[i] = __float2bfloat16(w - __bfloat162float(h));
    }
}

// ---------------- pack W2 [512][30] -> transposed padded [32][512] hi/lo ----------------
__global__ void pack2_kernel(const float* __restrict__ W2) {
    int i = blockIdx.x * blockDim.x + threadIdx.x;
    if (i < 32 * HH) {
        int n = i >> 9, k = i & 511;
        float w = (n < NACT) ? W2[k * NACT + n] : 0.f;
        __nv_bfloat16 h = __float2bfloat16(w);
        g_W2Th[i] = h;
        g_W2Tl[i] = __float2bfloat16(w - __bfloat162float(h));
    }
}

// ---------------- HMMA GEMM: C[M,N] = act(A @ WT^T + bias) ----------------
// All operands bf16 hi/lo in gmem. A split by K (A0* for k<K0, A1* after).
// Block tile 128x128x32, 8 warps (2x4), warp tile 64x32.
// Double-buffered smem, cp.async, ldmatrix. HILO: output hi/lo bf16 (else fp32).
#define GSTR 40
#define TILE_B (128 * GSTR * 2)      // 10240 bytes per sub-tile
#define BUF_B  (4 * TILE_B)          // 40960 per buffer
#define GEMM_SMEM (2 * BUF_B)        // 81920

template<bool RELU, bool HILO>
__global__ __launch_bounds__(256, 2)
void gemm_mma(const __nv_bfloat16* __restrict__ A0h, const __nv_bfloat16* __restrict__ A0l,
              int lda0, int K0,
              const __nv_bfloat16* __restrict__ A1h, const __nv_bfloat16* __restrict__ A1l,
              int lda1,
              const __nv_bfloat16* __restrict__ WTh, const __nv_bfloat16* __restrict__ WTl,
              const float* __restrict__ bias,
              float* __restrict__ C,
              __nv_bfloat16* __restrict__ Chi, __nv_bfloat16* __restrict__ Clo,
              int N, int K) {
    extern __shared__ char sm[];
    uint32_t sbase = (uint32_t)__cvta_generic_to_shared(sm);
    int tid = threadIdx.x;
    int wid = tid >> 5, lane = tid & 31;
    int gid = lane >> 2, tig = lane & 3;
    int wr = wid >> 2, wc = wid & 3;
    int rowC = blockIdx.y * 128;
    int colC = blockIdx.x * 128;

    int r = tid >> 1, kh = (tid & 1) * 16;

    int aRow = wr * 64 + (lane & 15);
    int aK   = (lane >> 4) * 8;
    int bRow = wc * 32 + (lane & 7);
    int bK   = ((lane >> 3) & 1) * 8;

    float acc[4][4][4];
    #pragma unroll
    for (int mi = 0; mi < 4; mi++)
        #pragma unroll
        for (int ni = 0; ni < 4; ni++)
            #pragma unroll
            for (int j = 0; j < 4; j++) acc[mi][ni][j] = 0.f;

    auto cp_chunk = [&](int kb, int b) {
        uint32_t off = (uint32_t)b * BUF_B + (uint32_t)(r * GSTR + kh) * 2;
        const __nv_bfloat16 *sh, *sl; int lda;
        if (kb < K0) { sh = A0h + kb; sl = A0l + kb; lda = lda0; }
        else         { sh = A1h + (kb - K0); sl = A1l + (kb - K0); lda = lda1; }
        const __nv_bfloat16* pah = sh + (size_t)(rowC + r) * lda + kh;
        const __nv_bfloat16* pal = sl + (size_t)(rowC + r) * lda + kh;
        CP16(sbase + off,               pah);
        CP16(sbase + off + 16,          pah + 8);
        CP16(sbase + TILE_B + off,      pal);
        CP16(sbase + TILE_B + off + 16, pal + 8);
        const __nv_bfloat16* pbh = WTh + (size_t)(colC + r) * K + kb + kh;
        const __nv_bfloat16* pbl = WTl + (size_t)(colC + r) * K + kb + kh;
        CP16(sbase + 2 * TILE_B + off,      pbh);
        CP16(sbase + 2 * TILE_B + off + 16, pbh + 8);
        CP16(sbase + 3 * TILE_B + off,      pbl);
        CP16(sbase + 3 * TILE_B + off + 16, pbl + 8);
        asm volatile("cp.async.commit_group;");
    };
    auto compute = [&](int b) {
        uint32_t base = sbase + b * BUF_B;
        #pragma unroll
        for (int ks = 0; ks < 32; ks += 16) {
            uint32_t bh[4][2], bl[4][2];
            #pragma unroll
            for (int ni = 0; ni < 4; ni++) {
                uint32_t ab = base + 2 * TILE_B + (uint32_t)((bRow + ni * 8) * GSTR + ks + bK) * 2;
                ldsm_x2(bh[ni], ab);
                ldsm_x2(bl[ni], ab + TILE_B);
            }
            #pragma unroll
            for (int mi = 0; mi < 4; mi++) {
                uint32_t aa = base + (uint32_t)((aRow + mi * 16) * GSTR + ks + aK) * 2;
                uint32_t a[4], al[4];
                ldsm_x4(a,  aa);
                ldsm_x4(al, aa + TILE_B);
                #pragma unroll
                for (int ni = 0; ni < 4; ni++) mma_bf16(acc[mi][ni], a,  bh[ni]);
                #pragma unroll
                for (int ni = 0; ni < 4; ni++) mma_bf16(acc[mi][ni], a,  bl[ni]);
                #pragma unroll
                for (int ni = 0; ni < 4; ni++) mma_bf16(acc[mi][ni], al, bh[ni]);
            }
        }
    };

    int nch = K / 32;
    cp_chunk(0, 0);
    for (int c = 0; c < nch; c++) {
        if (c + 1 < nch) {
            cp_chunk((c + 1) * 32, (c + 1) & 1);
            asm volatile("cp.async.wait_group 1;");
        } else {
            asm volatile("cp.async.wait_group 0;");
        }
        __syncthreads();
        compute(c & 1);
        __syncthreads();
    }

    // epilogue
    #pragma unroll
    for (int mi = 0; mi < 4; mi++) {
        int row0 = rowC + wr * 64 + mi * 16 + gid;
        #pragma unroll
        for (int ni = 0; ni < 4; ni++) {
            int col = colC + wc * 32 + ni * 8 + tig * 2;
            float bx = __ldg(&bias[col]), by = __ldg(&bias[col + 1]);
            float2 o0 = make_float2(acc[mi][ni][0] + bx, acc[mi][ni][1] + by);
            float2 o1 = make_float2(acc[mi][ni][2] + bx, acc[mi][ni][3] + by);
            if (RELU) {
                o0.x = fmaxf(o0.x, 0.f); o0.y = fmaxf(o0.y, 0.f);
                o1.x = fmaxf(o1.x, 0.f); o1.y = fmaxf(o1.y, 0.f);
            }
            if (HILO) {
                uint32_t h0, l0, h1, l1;
                cvt_hilo2(o0.x, o0.y, h0, l0);
                cvt_hilo2(o1.x, o1.y, h1, l1);
                size_t e0 = ((size_t)row0 * N + col) >> 1;
                size_t e1 = ((size_t)(row0 + 8) * N + col) >> 1;
                ((uint32_t*)Chi)[e0] = h0; ((uint32_t*)Clo)[e0] = l0;
                ((uint32_t*)Chi)[e1] = h1; ((uint32_t*)Clo)[e1] = l1;
            } else {
                *(float2*)(C + (size_t)row0 * N + col) = o0;
                *(float2*)(C + (size_t)(row0 + 8) * N + col) = o1;
            }
        }
    }
}

// ---------------- head as HMMA GEMM: q = comb @ W2T^T + b2; fused clip/S/ori_u/minmax ----------------
// Tile: 256 rows x 32 cols, K=512. 8 warps, warp tile 32x32. W2 resident in smem.
#define HSTR 40
#define HATILE (256 * HSTR * 2)      // 20480
#define HABUF  (2 * HATILE)          // 40960 (hi + lo)
#define W2STR  520
#define W2SM   (32 * W2STR * 2)      // 33280
#define W2HOFF (2 * HABUF)           // 81920
#define W2LOFF (W2HOFF + W2SM)
#define HEAD_SMEM (W2LOFF + W2SM)    // 148480

__global__ __launch_bounds__(256)
void head_mma(const __nv_bfloat16* __restrict__ Ah, const __nv_bfloat16* __restrict__ Al,
              const __nv_bfloat16* __restrict__ W2h, const __nv_bfloat16* __restrict__ W2l,
              const float* __restrict__ b2, float* __restrict__ out) {
    extern __shared__ char sm[];
    __shared__ float hsmx[8], hsmn[8];
    uint32_t sbase = (uint32_t)__cvta_generic_to_shared(sm);
    int tid = threadIdx.x;
    int wid = tid >> 5, lane = tid & 31;
    int gid = lane >> 2, tig = lane & 3;
    int rowC = blockIdx.x * 256;

    // load W2 hi/lo into padded smem (once)
    for (int idx = tid; idx < 32 * HH / 8; idx += 256) {
        int n = idx >> 6, kk = (idx & 63) * 8;
        uint32_t d = sbase + W2HOFF + (uint32_t)(n * W2STR + kk) * 2;
        *(uint4*)(sm + (d - sbase)) = ((const uint4*)W2h)[idx];
        *(uint4*)(sm + (d - sbase) + W2SM) = ((const uint4*)W2l)[idx];
    }

    float acc[2][4][4];
    #pragma unroll
    for (int mi = 0; mi < 2; mi++)
        #pragma unroll
        for (int ni = 0; ni < 4; ni++)
            #pragma unroll
            for (int j = 0; j < 4; j++) acc[mi][ni][j] = 0.f;

    auto cpA = [&](int kb, int b) {
        const __nv_bfloat16* ph = Ah + (size_t)(rowC + tid) * HH + kb;
        const __nv_bfloat16* pl = Al + (size_t)(rowC + tid) * HH + kb;
        uint32_t off = sbase + (uint32_t)b * HABUF + (uint32_t)tid * HSTR * 2;
        CP16(off,      ph);      CP16(off + 16, ph + 8);
        CP16(off + 32, ph + 16); CP16(off + 48, ph + 24);
        uint32_t offl = off + HATILE;
        CP16(offl,      pl);      CP16(offl + 16, pl + 8);
        CP16(offl + 32, pl + 16); CP16(offl + 48, pl + 24);
        asm volatile("cp.async.commit_group;");
    };
    auto compute = [&](int b, int kb) {
        uint32_t abase = sbase + b * HABUF;
        #pragma unroll
        for (int ks = 0; ks < 32; ks += 16) {
            uint32_t bh[4][2], bl[4][2];
            #pragma unroll
            for (int ni = 0; ni < 4; ni++) {
                uint32_t ab = sbase + W2HOFF +
                    (uint32_t)((ni * 8 + (lane & 7)) * W2STR + kb + ks + ((lane >> 3) & 1) * 8) * 2;
                ldsm_x2(bh[ni], ab);
                ldsm_x2(bl[ni], ab + W2SM);
            }
            #pragma unroll
            for (int mi = 0; mi < 2; mi++) {
                uint32_t aa = abase +
                    (uint32_t)((wid * 32 + mi * 16 + (lane & 15)) * HSTR + ks + (lane >> 4) * 8) * 2;
                uint32_t a[4], al[4];
                ldsm_x4(a,  aa);
                ldsm_x4(al, aa + HATILE);
                #pragma unroll
                for (int ni = 0; ni < 4; ni++) mma_bf16(acc[mi][ni], a,  bh[ni]);
                #pragma unroll
                for (int ni = 0; ni < 4; ni++) mma_bf16(acc[mi][ni], a,  bl[ni]);
                #pragma unroll
                for (int ni = 0; ni < 4; ni++) mma_bf16(acc[mi][ni], al, bh[ni]);
            }
        }
    };

    cpA(0, 0);
    for (int c = 0; c < HH / 32; c++) {
        if (c + 1 < HH / 32) {
            cpA((c + 1) * 32, (c + 1) & 1);
            asm volatile("cp.async.wait_group 1;");
        } else {
            asm volatile("cp.async.wait_group 0;");
        }
        __syncthreads();
        compute(c & 1, c * 32);
        __syncthreads();
    }

    // stage be into smem (stride 33 to avoid bank conflicts)
    float* sbe = (float*)sm;
    #pragma unroll
    for (int mi = 0; mi < 2; mi++) {
        int r0 = wid * 32 + mi * 16 + gid;
        #pragma unroll
        for (int ni = 0; ni < 4; ni++) {
            int c0 = ni * 8 + tig * 2;
            float bx = (c0 < NACT) ? __ldg(&b2[c0]) : 0.f;
            float by = (c0 + 1 < NACT) ? __ldg(&b2[c0 + 1]) : 0.f;
            sbe[r0 * 33 + c0]           = fmaxf(acc[mi][ni][0] + bx, 0.f);
            sbe[r0 * 33 + c0 + 1]       = fmaxf(acc[mi][ni][1] + by, 0.f);
            sbe[(r0 + 8) * 33 + c0]     = fmaxf(acc[mi][ni][2] + bx, 0.f);
            sbe[(r0 + 8) * 33 + c0 + 1] = fmaxf(acc[mi][ni][3] + by, 0.f);
        }
    }
    __syncthreads();

    // one thread per row: write be, row-sum -> ori_u, min/max
    int row = rowC + tid;
    float s = 0.f, mn = 1e30f, mx = -1e30f;
    #pragma unroll
    for (int n = 0; n < NACT; n++) {
        float v = sbe[tid * 33 + n];
        s += v; mn = fminf(mn, v); mx = fmaxf(mx, v);
        out[(size_t)row * NACT + n] = v;
    }
    out[ORI_OFF + (row & 7) * BB + (row >> 3)] = (float)NACT / (s + (float)NACT);
    #pragma unroll
    for (int o = 16; o; o >>= 1) {
        mx = fmaxf(mx, __shfl_xor_sync(0xFFFFFFFFu, mx, o));
        mn = fminf(mn, __shfl_xor_sync(0xFFFFFFFFu, mn, o));
    }
    if (lane == 0) { hsmx[wid] = mx; hsmn[wid] = mn; }
    __syncthreads();
    if (tid == 0) {
        float M = -1e30f, m = 1e30f;
        #pragma unroll
        for (int i = 0; i < 8; i++) { M = fmaxf(M, hsmx[i]); m = fminf(m, hsmn[i]); }
        atomicMax(&g_scal[0], fkey(M));
        atomicMin(&g_scal[1], fkey(m));
    }
}

// ---------------- per-batch attention (writes hi/lo bf16) ----------------
__global__ __launch_bounds__(256)
void attn_kernel(const float* __restrict__ kvq, const float* __restrict__ Wattn,
                 const float* __restrict__ battn) {
    int b = blockIdx.x;
    int tid = threadIdx.x;
    __shared__ float sk[AA * NKv];
    __shared__ float sq[AA * NQv];
    __shared__ float sv[AA * NVv];
    __shared__ float slog[AA][AA];
    __shared__ float swt[AA][AA + 1];
    __shared__ float skp[AA];
    const float* base = kvq + (size_t)b * AA * HH;
    {
        int a = tid >> 5, c = (tid & 31) * 4;
        *(float4*)&sk[a * NKv + c] = *(const float4*)&base[a * HH + c];
        *(float4*)&sq[a * NQv + c] = *(const float4*)&base[a * HH + 384 + c];
    }
    for (int i = tid; i < AA * NVv / 4; i += 256) {
        int a = i >> 6, c = (i & 63) * 4;
        *(float4*)&sv[a * NVv + c] = *(const float4*)&base[a * HH + 128 + c];
    }
    __syncthreads();
    int w = tid >> 5, lane = tid & 31;
    float kp = 0.f;
    for (int i = lane; i < AA * NKv; i += 32)
        kp += sk[i] * __ldg(&Wattn[(NQv + i) * AA + w]);
    #pragma unroll
    for (int o = 16; o; o >>= 1) kp += __shfl_xor_sync(0xFFFFFFFFu, kp, o);
    if (lane == 0) skp[w] = kp;
    __syncthreads();
    float accj[AA] = {0,0,0,0,0,0,0,0};
    for (int q = lane; q < NQv; q += 32) {
        float qv = sq[w * NQv + q];
        #pragma unroll
        for (int j = 0; j < AA; j++) accj[j] += qv * __ldg(&Wattn[q * AA + j]);
    }
    #pragma unroll
    for (int j = 0; j < AA; j++) {
        float v = accj[j];
        #pragma unroll
        for (int o = 16; o; o >>= 1) v += __shfl_xor_sync(0xFFFFFFFFu, v, o);
        if (lane == 0) slog[w][j] = v + skp[j] + __ldg(&battn[j]);
    }
    __syncthreads();
    if (tid < AA) {
        float m = -1e30f;
        #pragma unroll
        for (int j = 0; j < AA; j++) m = fmaxf(m, slog[tid][j]);
        float e[AA], s = 0.f;
        #pragma unroll
        for (int j = 0; j < AA; j++) { e[j] = expf(slog[tid][j] - m); s += e[j]; }
        #pragma unroll
        for (int j = 0; j < AA; j++) swt[tid][j] = e[j] / s;
    }
    __syncthreads();
    for (int idx = tid; idx < AA * NVv / 4; idx += 256) {
        int a = idx >> 6, v = (idx & 63) * 4;
        float4 acc = make_float4(0.f, 0.f, 0.f, 0.f);
        #pragma unroll
        for (int j = 0; j < AA; j++) {
            float wt = swt[a][j];
            float4 s4 = *(const float4*)&sv[j * NVv + v];
            acc.x += wt * s4.x; acc.y += wt * s4.y;
            acc.z += wt * s4.z; acc.w += wt * s4.w;
        }
        uint32_t h01, l01, h23, l23;
        cvt_hilo2(acc.x, acc.y, h01, l01);
        cvt_hilo2(acc.z, acc.w, h23, l23);
        size_t elem = (size_t)(b * AA + a) * NVv + v;
        ((uint2*)g_ATh)[elem >> 2] = make_uint2(h01, h23);
        ((uint2*)g_ATl)[elem >> 2] = make_uint2(l01, l23);
    }
}

// ---------------- Dempster-Shafer scan ----------------
__global__ __launch_bounds__(256)
void ds_kernel(const float* __restrict__ out, float* __restrict__ allev) {
    __shared__ float smx[8], smn[8];
    int w = threadIdx.x >> 5, lane = threadIdx.x & 31;
    int b = blockIdx.x * 8 + w;
    float b0 = 0.f, u0 = 1.f;
    for (int a = 0; a < AA; a++) {
        float e = (lane < NACT) ? out[(size_t)(b * AA + a) * NACT + lane] : 0.f;
        float s = e;
        #pragma unroll
        for (int o = 16; o; o >>= 1) s += __shfl_xor_sync(0xFFFFFFFFu, s, o);
        s += (float)NACT;
        float b1 = e / s;
        float u1 = (float)NACT / s;
        float sum0 = b0, sum1 = b1, dot = b0 * b1;
        #pragma unroll
        for (int o = 16; o; o >>= 1) {
            sum0 += __shfl_xor_sync(0xFFFFFFFFu, sum0, o);
            sum1 += __shfl_xor_sync(0xFFFFFFFFu, sum1, o);
            dot  += __shfl_xor_sync(0xFFFFFFFFu, dot,  o);
        }
        float Cc = sum0 * sum1 - dot;
        float denom = 1.f - Cc;
        float nb = (b0 * b1 + b0 * u1 + b1 * u0) / denom;
        u0 = (u0 * u1) / denom;
        b0 = nb;
    }
    float ev = b0 * ((float)NACT / u0);
    if (lane < NACT) allev[(size_t)b * NACT + lane] = ev;
    float mx = (lane < NACT) ? ev : -1e30f;
    float mn = (lane < NACT) ? ev : 1e30f;
    #pragma unroll
    for (int o = 16; o; o >>= 1) {
        mx = fmaxf(mx, __shfl_xor_sync(0xFFFFFFFFu, mx, o));
        mn = fminf(mn, __shfl_xor_sync(0xFFFFFFFFu, mn, o));
    }
    if (lane == 0) { smx[w] = mx; smn[w] = mn; }
    __syncthreads();
    if (threadIdx.x == 0) {
        float M = -1e30f, m = 1e30f;
        #pragma unroll
        for (int i = 0; i < 8; i++) { M = fmaxf(M, smx[i]); m = fminf(m, smn[i]); }
        atomicMax(&g_scal[2], fkey(M));
        atomicMin(&g_scal[3], fkey(m));
    }
}

// ---------------- finalize ----------------
__global__ __launch_bounds__(256)
void fin_kernel(float* __restrict__ out, const float* __restrict__ allev) {
    float maxbe = funkey(g_scal[0]);
    float minbe = funkey(g_scal[1]);
    float maxre = funkey(g_scal[2]);
    float minre = funkey(g_scal[3]);
    float scale = (maxbe - minbe) * 0.1f;
    float norm = scale / (maxre - minre + 0.01f);
    int w = threadIdx.x >> 5, lane = threadIdx.x & 31;
    int row = blockIdx.x * 8 + w;
    int b = row >> 3, a = row & 7;
    float be = (lane < NACT) ? out[(size_t)row * NACT + lane] : 0.f;
    float ev = (lane < NACT) ? allev[(size_t)b * NACT + lane] : 0.f;
    float re = (ev - minre) * norm;
    float combined = be + re;
    if (lane < NACT) out[(size_t)row * NACT + lane] = be + combined;
    float s = (lane < NACT) ? combined : 0.f;
    #pragma unroll
    for (int o = 16; o; o >>= 1) s += __shfl_xor_sync(0xFFFFFFFFu, s, o);
    s += (float)NACT;
    if (lane == 0) out[COM_OFF + a * BB + b] = (float)NACT / s;
}

// ---------------- launch ----------------
extern "C" void kernel_launch(void* const* d_in, const int* in_sizes, int n_in,
                              void* d_out, int out_size) {
    const float* hidden = (const float*)d_in[0];
    const float* Wk    = (const float*)d_in[2];
    const float* bk    = (const float*)d_in[3];
    const float* Wv    = (const float*)d_in[4];
    const float* bv    = (const float*)d_in[5];
    const float* Wq    = (const float*)d_in[6];
    const float* bq    = (const float*)d_in[7];
    const float* Wattn = (const float*)d_in[8];
    const float* battn = (const float*)d_in[9];
    const float* Wc    = (const float*)d_in[10];
    const float* bc    = (const float*)d_in[11];
    const float* W2    = (const float*)d_in[12];
    const float* b2    = (const float*)d_in[13];
    float* out = (float*)d_out;

    float *kvq, *allev, *b1;
    __nv_bfloat16 *ah, *al, *ath, *atl, *ch, *cl, *wt1h, *wt1l, *wtch, *wtcl, *w2h, *w2l;
    cudaGetSymbolAddress((void**)&kvq,   g_kvq);
    cudaGetSymbolAddress((void**)&allev, g_allev);
    cudaGetSymbolAddress((void**)&b1,    g_b1);
    cudaGetSymbolAddress((void**)&ah,    g_Ah);
    cudaGetSymbolAddress((void**)&al,    g_Al);
    cudaGetSymbolAddress((void**)&ath,   g_ATh);
    cudaGetSymbolAddress((void**)&atl,   g_ATl);
    cudaGetSymbolAddress((void**)&ch,    g_Ch);
    cudaGetSymbolAddress((void**)&cl,    g_Cl);
    cudaGetSymbolAddress((void**)&wt1h,  g_WT1h);
    cudaGetSymbolAddress((void**)&wt1l,  g_WT1l);
    cudaGetSymbolAddress((void**)&wtch,  g_WTch);
    cudaGetSymbolAddress((void**)&wtcl,  g_WTcl);
    cudaGetSymbolAddress((void**)&w2h,   g_W2Th);
    cudaGetSymbolAddress((void**)&w2l,   g_W2Tl);

    cudaFuncSetAttribute(gemm_mma<false,false>, cudaFuncAttributeMaxDynamicSharedMemorySize, GEMM_SMEM);
    cudaFuncSetAttribute(gemm_mma<true,true>,   cudaFuncAttributeMaxDynamicSharedMemorySize, GEMM_SMEM);
    cudaFuncSetAttribute(head_mma,              cudaFuncAttributeMaxDynamicSharedMemorySize, HEAD_SMEM);

    init_kernel<<<1, 32>>>();
    convA_kernel<<<ROWS * HH / 4 / 256, 256>>>(hidden);
    pack1_kernel<<<(HH * HH + 255) / 256, 256>>>(Wk, bk, Wv, bv, Wq, bq);
    packc_kernel<<<(HH * (NVv + HH) + 255) / 256, 256>>>(Wc);
    pack2_kernel<<<(32 * HH + 255) / 256, 256>>>(W2);

    dim3 g1(HH / 128, ROWS / 128);   // (4, 256)
    gemm_mma<false,false><<<g1, 256, GEMM_SMEM>>>(ah, al, HH, HH, ah, al, HH,
                                                  wt1h, wt1l, b1, kvq, nullptr, nullptr, HH, HH);

    attn_kernel<<<BB, 256>>>(kvq, Wattn, battn);

    gemm_mma<true,true><<<g1, 256, GEMM_SMEM>>>(ath, atl, NVv, NVv, ah, al, HH,
                                                wtch, wtcl, bc, nullptr, ch, cl, HH, NVv + HH);

    head_mma<<<ROWS / 256, 256, HEAD_SMEM>>>(ch, cl, w2h, w2l, b2, out);
    ds_kernel<<<BB / 8, 256>>>(out, allev);
    fin_kernel<<<ROWS / 8, 256>>>(out, allev);
}